// round 4
// baseline (speedup 1.0000x reference)
#include <cuda_runtime.h>
#include <cstdint>
#include <math.h>

#define BSZ   4096
#define NIN   784
#define H1    100
#define H2    10
#define TSTEPS 100
#define TBEGIN 20

#define RPB   16            // rows per CTA
#define NBLK  (BSZ / RPB)   // 256 CTAs -> 2 per SM
#define NTH   384           // 12 warps: 0-3 consumers (100 active) + layer2; 4-11 producers
#define NCONS 128
#define NPROD 256
#define BK    28
#define NKT   (NIN / BK)    // 28
#define NCELL (RPB * H2)    // 160 layer2 cells per CTA

// ---- JAX threefry2x32 (20 rounds), exact ----
__device__ __forceinline__ void tf2x32(uint32_t k0, uint32_t k1,
                                       uint32_t c0, uint32_t c1,
                                       uint32_t& o0, uint32_t& o1) {
    const uint32_t ks2 = k0 ^ k1 ^ 0x1BD11BDAu;
    uint32_t x0 = c0 + k0;
    uint32_t x1 = c1 + k1;
#define TF_RND(r) { x0 += x1; x1 = __funnelshift_l(x1, x1, (r)); x1 ^= x0; }
    TF_RND(13) TF_RND(15) TF_RND(26) TF_RND(6)
    x0 += k1;  x1 += ks2 + 1u;
    TF_RND(17) TF_RND(29) TF_RND(16) TF_RND(24)
    x0 += ks2; x1 += k0 + 2u;
    TF_RND(13) TF_RND(15) TF_RND(26) TF_RND(6)
    x0 += k0;  x1 += k1 + 3u;
    TF_RND(17) TF_RND(29) TF_RND(16) TF_RND(24)
    x0 += k1;  x1 += ks2 + 4u;
    TF_RND(13) TF_RND(15) TF_RND(26) TF_RND(6)
    x0 += ks2; x1 += k0 + 5u;
#undef TF_RND
    o0 = x0; o1 = x1;
}

__device__ __forceinline__ float tf_uniform(uint32_t key0, uint32_t key1, uint32_t idx) {
    uint32_t y0, y1;
    tf2x32(key0, key1, 0u, idx, y0, y1);
    uint32_t bits = y0 ^ y1;
    return __uint_as_float((bits >> 9) | 0x3f800000u) - 1.0f;
}

// packed fp32x2 helpers (each lane = exact IEEE fp32 -> bitwise same as scalar fmaf)
#define DUP64(d, f)  asm("mov.b64 %0, {%1, %1};" : "=l"(d) : "r"(__float_as_uint(f)))
#define FMA2(c, a, b) asm("fma.rn.f32x2 %0, %1, %2, %0;" : "+l"(c) : "l"(a), "l"(b))
#define UNPK(lo, hi, v) asm("mov.b64 {%0, %1}, %2;" : "=r"(lo), "=r"(hi) : "l"(v))

__global__ void __launch_bounds__(NTH, 2)
spiking_all(const float* __restrict__ x,  const float* __restrict__ W1,
            const float* __restrict__ b1, const float* __restrict__ W2,
            const float* __restrict__ b2, float* __restrict__ out)
{
    __shared__ __align__(16) float s_a[2][RPB][BK];      // 3.6 KB (A = u.*x tiles)
    __shared__ __align__(16) float s_b[2][BK][H1 + 4];   // 23.3 KB (W1 tiles, 416B rows)
    __shared__ float s_outer1[RPB][H1];                  // 6.4 KB (layer1 spikes)
    __shared__ float s_w2[H1 * H2];                      // 4 KB
    __shared__ float s_b1[H1];
    __shared__ float s_b2[H2];
    __shared__ float s_oacc[NCELL];

    const int tid  = threadIdx.x;
    const int r0   = blockIdx.x * RPB;
    const int ptid = tid - NCONS;          // producer index (tid >= 128)
    const int rg   = tid / 25;             // consumer: rows rg*4..rg*4+3 (tid<100)
    const int cg   = tid - rg * 25;        // consumer: cols cg*4..cg*4+3

    // ---- init params & state ----
    for (int i = tid; i < H1 * H2; i += NTH) s_w2[i] = W2[i];
    for (int i = tid; i < H1;      i += NTH) s_b1[i] = b1[i];
    if (tid < H2) s_b2[tid] = b2[tid];
    for (int i = tid; i < RPB * H1; i += NTH) ((float*)s_outer1)[i] = 0.f;

    // layer2 state: cell = localrow*10+col. tid<128 owns cell tid; tid<32 also cell 128+tid.
    float i2a = 0.f, acca = 0.f, i2b = 0.f, accb = 0.f;
    // layer1 membrane state (consumer threads, 16 cells each)
    float inn[4][4] = {};
    unsigned long long acc2[4][2];

    __syncthreads();

    for (int t = 0; t < TSTEPS; t++) {
        uint32_t key0, key1;
        tf2x32(0u, 42u, 0u, (uint32_t)t, key0, key1);   // partitionable split

        // ---- phase A (overlapped): warps 0-3 do layer2 on PREVIOUS outer1,
        //      producers fill pipeline buffer 0 for kt=0 ----
        if (tid < NCONS) {
            #pragma unroll
            for (int half = 0; half < 2; half++) {
                if (half == 1 && tid >= NCELL - NCONS) break;
                const int o   = half ? (NCONS + tid) : tid;
                const int lr  = o / H2, n = o - lr * H2;
                float& i2R  = half ? i2b  : i2a;
                float& accR = half ? accb : acca;
                float acc = 0.f;
                const float* __restrict__ po = &s_outer1[lr][0];
                #pragma unroll 4
                for (int j = 0; j < H1; j++)
                    acc = __fadd_rn(acc, __fmul_rn(po[j], s_w2[j * H2 + n]));
                const float exc = __fadd_rn(acc, s_b2[n]);
                if (t >= TBEGIN) accR = __fadd_rn(accR, i2R);
                const float pre  = __fadd_rn(exc, __fmul_rn(i2R, 0.9f));
                const float gate = (pre > 1.0f) ? 1.0f : 0.0f;
                i2R = __fsub_rn(pre, __fmul_rn(gate, __fmul_rn(1.5f, pre)));
            }
            #pragma unroll
            for (int i = 0; i < 4; i++) { acc2[i][0] = 0ull; acc2[i][1] = 0ull; }
        } else {
            // produce tile 0 into buffer 0
            for (int i = ptid; i < RPB * BK; i += NPROD) {
                const int r = i / BK, kk = i - r * BK;
                const uint32_t idx = (uint32_t)((r0 + r) * NIN + kk);
                const float u = tf_uniform(key0, key1, idx);
                s_a[0][r][kk] = __fmul_rn(u, x[idx]);
            }
            for (int i = ptid; i < BK * 25; i += NPROD) {
                const int kk = i / 25, m = i - kk * 25;
                *(float4*)&s_b[0][kk][m * 4] = *(const float4*)&W1[kk * H1 + m * 4];
            }
        }
        __syncthreads();

        // ---- pipelined k-loop: consumers MAC buf[kt&1], producers fill buf[(kt+1)&1] ----
        for (int kt = 0; kt < NKT; kt++) {
            const int buf = kt & 1;
            if (tid < 100) {
                #pragma unroll
                for (int g = 0; g < BK; g += 4) {
                    float4 a0 = *(const float4*)&s_a[buf][rg * 4 + 0][g];
                    float4 a1 = *(const float4*)&s_a[buf][rg * 4 + 1][g];
                    float4 a2 = *(const float4*)&s_a[buf][rg * 4 + 2][g];
                    float4 a3 = *(const float4*)&s_a[buf][rg * 4 + 3][g];
                    ulonglong2 B0 = *(const ulonglong2*)&s_b[buf][g + 0][cg * 4];
                    ulonglong2 B1 = *(const ulonglong2*)&s_b[buf][g + 1][cg * 4];
                    ulonglong2 B2 = *(const ulonglong2*)&s_b[buf][g + 2][cg * 4];
                    ulonglong2 B3 = *(const ulonglong2*)&s_b[buf][g + 3][cg * 4];
                    #define MACROW(ai, i_) { \
                        unsigned long long dx, dy, dz, dw; \
                        DUP64(dx, ai.x); DUP64(dy, ai.y); DUP64(dz, ai.z); DUP64(dw, ai.w); \
                        FMA2(acc2[i_][0], dx, B0.x); FMA2(acc2[i_][0], dy, B1.x); \
                        FMA2(acc2[i_][0], dz, B2.x); FMA2(acc2[i_][0], dw, B3.x); \
                        FMA2(acc2[i_][1], dx, B0.y); FMA2(acc2[i_][1], dy, B1.y); \
                        FMA2(acc2[i_][1], dz, B2.y); FMA2(acc2[i_][1], dw, B3.y); }
                    MACROW(a0, 0) MACROW(a1, 1) MACROW(a2, 2) MACROW(a3, 3)
                    #undef MACROW
                }
            } else if (tid >= NCONS && kt < NKT - 1) {
                const int k0 = (kt + 1) * BK;
                const int nbuf = buf ^ 1;
                for (int i = ptid; i < RPB * BK; i += NPROD) {
                    const int r = i / BK, kk = i - r * BK;
                    const uint32_t idx = (uint32_t)((r0 + r) * NIN + k0 + kk);
                    const float u = tf_uniform(key0, key1, idx);
                    s_a[nbuf][r][kk] = __fmul_rn(u, x[idx]);
                }
                for (int i = ptid; i < BK * 25; i += NPROD) {
                    const int kk = i / 25, m = i - kk * 25;
                    *(float4*)&s_b[nbuf][kk][m * 4] =
                        *(const float4*)&W1[(k0 + kk) * H1 + m * 4];
                }
            }
            __syncthreads();
        }

        // ---- layer1 state update (same rounding chain, bitwise) ----
        if (tid < 100) {
            #pragma unroll
            for (int i = 0; i < 4; i++) {
                const int lr = rg * 4 + i;
                #pragma unroll
                for (int p = 0; p < 2; p++) {
                    uint32_t ulo, uhi;
                    UNPK(ulo, uhi, acc2[i][p]);
                    #pragma unroll
                    for (int q = 0; q < 2; q++) {
                        const int   c    = cg * 4 + p * 2 + q;
                        const float accv = __uint_as_float(q ? uhi : ulo);
                        const float exc  = __fadd_rn(accv, s_b1[c]);
                        const float pre  = __fadd_rn(exc, __fmul_rn(inn[i][p * 2 + q], 0.9f));
                        const float outv = fmaxf(__fsub_rn(pre, 1.0f), 0.f);
                        const float gate = (pre > 1.0f) ? 1.0f : 0.0f;
                        inn[i][p * 2 + q] = __fsub_rn(pre, __fmul_rn(gate, __fmul_rn(1.5f, pre)));
                        s_outer1[lr][c] = outv;
                    }
                }
            }
        }
        __syncthreads();   // order state-update writes before next step's layer2 reads
    }

    // ---- epilogue: log_softmax per row ----
    if (tid < NCONS) s_oacc[tid] = acca;
    if (tid < NCELL - NCONS) s_oacc[NCONS + tid] = accb;
    __syncthreads();
    if (tid < RPB) {
        float v[H2];
        float m = -INFINITY;
        #pragma unroll
        for (int n = 0; n < H2; n++) { v[n] = s_oacc[tid * H2 + n]; m = fmaxf(m, v[n]); }
        float s = 0.f;
        #pragma unroll
        for (int n = 0; n < H2; n++) s += expf(v[n] - m);
        const float ls = logf(s);
        #pragma unroll
        for (int n = 0; n < H2; n++) out[(r0 + tid) * H2 + n] = v[n] - m - ls;
    }
}

extern "C" void kernel_launch(void* const* d_in, const int* in_sizes, int n_in,
                              void* d_out, int out_size) {
    const float* x  = (const float*)d_in[0];
    const float* W1 = (const float*)d_in[1];
    const float* b1 = (const float*)d_in[2];
    const float* W2 = (const float*)d_in[3];
    const float* b2 = (const float*)d_in[4];
    spiking_all<<<NBLK, NTH>>>(x, W1, b1, W2, b2, (float*)d_out);
}

// round 5
// speedup vs baseline: 1.0489x; 1.0489x over previous
#include <cuda_runtime.h>
#include <cstdint>
#include <math.h>

#define BSZ    4096
#define NIN    784
#define H1     100
#define H2     10
#define TSTEPS 100
#define TBEGIN 20

#define RPB    16               // rows per CTA
#define NBLK   (BSZ / RPB)      // 256 CTAs -> 2 per SM
#define NTH    384              // warps 0-3 consumers (128 thr), 4-11 producers (256 thr)
#define NCONS  128
#define NPROD  256
#define BK     28
#define NKT    (NIN / BK)       // 28
#define NSTAGE 2
#define NCELL  (RPB * H2)       // 160
#define NTILES (TSTEPS * NKT)   // 2800

// ---- JAX threefry2x32 (20 rounds), exact ----
__device__ __forceinline__ void tf2x32(uint32_t k0, uint32_t k1,
                                       uint32_t c0, uint32_t c1,
                                       uint32_t& o0, uint32_t& o1) {
    const uint32_t ks2 = k0 ^ k1 ^ 0x1BD11BDAu;
    uint32_t x0 = c0 + k0;
    uint32_t x1 = c1 + k1;
#define TF_RND(r) { x0 += x1; x1 = __funnelshift_l(x1, x1, (r)); x1 ^= x0; }
    TF_RND(13) TF_RND(15) TF_RND(26) TF_RND(6)
    x0 += k1;  x1 += ks2 + 1u;
    TF_RND(17) TF_RND(29) TF_RND(16) TF_RND(24)
    x0 += ks2; x1 += k0 + 2u;
    TF_RND(13) TF_RND(15) TF_RND(26) TF_RND(6)
    x0 += k0;  x1 += k1 + 3u;
    TF_RND(17) TF_RND(29) TF_RND(16) TF_RND(24)
    x0 += k1;  x1 += ks2 + 4u;
    TF_RND(13) TF_RND(15) TF_RND(26) TF_RND(6)
    x0 += ks2; x1 += k0 + 5u;
#undef TF_RND
    o0 = x0; o1 = x1;
}

__device__ __forceinline__ float tf_uniform(uint32_t key0, uint32_t key1, uint32_t idx) {
    uint32_t y0, y1;
    tf2x32(key0, key1, 0u, idx, y0, y1);
    uint32_t bits = y0 ^ y1;
    return __uint_as_float((bits >> 9) | 0x3f800000u) - 1.0f;
}

// packed fp32x2 (each lane exact IEEE fp32 -> bitwise same as scalar fmaf chain)
#define DUP64(d, f)  asm("mov.b64 %0, {%1, %1};" : "=l"(d) : "r"(__float_as_uint(f)))
#define FMA2(c, a, b) asm("fma.rn.f32x2 %0, %1, %2, %0;" : "+l"(c) : "l"(a), "l"(b))
#define UNPK(lo, hi, v) asm("mov.b64 {%0, %1}, %2;" : "=r"(lo), "=r"(hi) : "l"(v))

// ---- mbarrier helpers ----
__device__ __forceinline__ uint32_t smem_u32(const void* p) {
    return (uint32_t)__cvta_generic_to_shared(p);
}
#define MBAR_INIT(a, c) \
    asm volatile("mbarrier.init.shared.b64 [%0], %1;" :: "r"(a), "r"(c) : "memory")
#define MBAR_ARRIVE(a) \
    asm volatile("mbarrier.arrive.shared.b64 _, [%0];" :: "r"(a) : "memory")
#define MBAR_WAIT(a, ph) do {                                              \
    uint32_t _m = (a), _p = (ph), _done;                                   \
    asm volatile("{\n\t.reg .pred p;\n\t"                                  \
        "mbarrier.try_wait.parity.acquire.cta.shared::cta.b64 p, [%1], %2;\n\t" \
        "selp.b32 %0, 1, 0, p;\n\t}"                                       \
        : "=r"(_done) : "r"(_m), "r"(_p) : "memory");                      \
    if (!_done) {                                                          \
        asm volatile("{\n\t.reg .pred P1;\n\t"                             \
            "WL_%=:\n\t"                                                   \
            "mbarrier.try_wait.parity.acquire.cta.shared::cta.b64 P1, [%0], %1, 0x989680;\n\t" \
            "@P1 bra.uni WD_%=;\n\t"                                       \
            "bra.uni WL_%=;\n\t"                                           \
            "WD_%=:\n\t}" :: "r"(_m), "r"(_p) : "memory");                 \
    }                                                                      \
} while (0)
#define BAR1_128() asm volatile("bar.sync 1, 128;" ::: "memory")

__global__ void __launch_bounds__(NTH, 2)
spiking_all(const float* __restrict__ x,  const float* __restrict__ W1,
            const float* __restrict__ b1, const float* __restrict__ W2,
            const float* __restrict__ b2, float* __restrict__ out)
{
    __shared__ __align__(16) float s_a[NSTAGE][RPB][BK];   // 3.6 KB (112B rows)
    __shared__ __align__(16) float s_b[NSTAGE][BK][H1];    // 22.4 KB (400B rows)
    __shared__ float s_outer1[RPB][H1];                    // 6.4 KB
    __shared__ float s_w2[H1 * H2];                        // 4 KB
    __shared__ float s_b1[H1];
    __shared__ float s_b2[H2];
    __shared__ float s_oacc[NCELL];
    __shared__ __align__(8) unsigned long long s_mbar[2 * NSTAGE]; // full[0..1], empty[0..1]

    const int tid = threadIdx.x;
    const int r0  = blockIdx.x * RPB;

    if (tid == 0) {
        #pragma unroll
        for (int s = 0; s < NSTAGE; s++) {
            MBAR_INIT(smem_u32(&s_mbar[s]), NPROD);            // full[s]
            MBAR_INIT(smem_u32(&s_mbar[NSTAGE + s]), NCONS);   // empty[s]
        }
    }
    for (int i = tid; i < H1 * H2; i += NTH) s_w2[i] = W2[i];
    for (int i = tid; i < H1;      i += NTH) s_b1[i] = b1[i];
    if (tid < H2) s_b2[tid] = b2[tid];
    for (int i = tid; i < RPB * H1; i += NTH) ((float*)s_outer1)[i] = 0.f;
    __syncthreads();

    // ================= producers: autonomous 2800-tile stream =================
    if (tid >= NCONS) {
        const int ptid = tid - NCONS;
        int stage = 0, phase = 1;            // parity trick: first waits pass
        uint32_t key0 = 0, key1 = 0;
        for (int gt = 0; gt < NTILES; gt++) {
            const int t  = gt / NKT;
            const int kt = gt - t * NKT;
            if (kt == 0) tf2x32(0u, 42u, 0u, (uint32_t)t, key0, key1);
            const int k0 = kt * BK;
            MBAR_WAIT(smem_u32(&s_mbar[NSTAGE + stage]), phase);
            for (int i = ptid; i < RPB * BK; i += NPROD) {
                const int r = i / BK, kk = i - r * BK;
                const uint32_t idx = (uint32_t)((r0 + r) * NIN + k0 + kk);
                const float u = tf_uniform(key0, key1, idx);
                s_a[stage][r][kk] = __fmul_rn(u, x[idx]);
            }
            for (int i = ptid; i < BK * 25; i += NPROD) {
                const int kk = i / 25, m = i - kk * 25;
                *(float4*)&s_b[stage][kk][m * 4] =
                    *(const float4*)&W1[(k0 + kk) * H1 + m * 4];
            }
            MBAR_ARRIVE(smem_u32(&s_mbar[stage]));
            if (++stage == NSTAGE) { stage = 0; phase ^= 1; }
        }
        return;
    }

    // ================= consumers (tid < 128) =================
    // warp-remapped tiling: cg = tid>>2 (col group, <25 active), row base = (tid&3)*4
    const int  cg  = tid >> 2;
    const int  rb  = (tid & 3) * 4;
    const bool mac = (tid < 100);

    float i2a = 0.f, acca = 0.f, i2b = 0.f, accb = 0.f;   // layer2 cells tid, 128+tid
    float inn[4][4] = {};
    unsigned long long acc2[4][2];
    int stage = 0, phase = 0;

    for (int t = 0; t < TSTEPS; t++) {
        // ---- layer2 on PREVIOUS step's outer1 (delayed semantics) ----
        #pragma unroll
        for (int half = 0; half < 2; half++) {
            if (half == 1 && tid >= NCELL - NCONS) break;
            const int o  = half ? (NCONS + tid) : tid;
            const int lr = o / H2, n = o - lr * H2;
            float& i2R  = half ? i2b  : i2a;
            float& accR = half ? accb : acca;
            float acc = 0.f;
            const float* __restrict__ po = &s_outer1[lr][0];
            #pragma unroll 4
            for (int j = 0; j < H1; j++)
                acc = __fadd_rn(acc, __fmul_rn(po[j], s_w2[j * H2 + n]));
            const float exc = __fadd_rn(acc, s_b2[n]);
            if (t >= TBEGIN) accR = __fadd_rn(accR, i2R);
            const float pre  = __fadd_rn(exc, __fmul_rn(i2R, 0.9f));
            const float gate = (pre > 1.0f) ? 1.0f : 0.0f;
            i2R = __fsub_rn(pre, __fmul_rn(gate, __fmul_rn(1.5f, pre)));
        }
        if (mac) {
            #pragma unroll
            for (int i = 0; i < 4; i++) { acc2[i][0] = 0ull; acc2[i][1] = 0ull; }
        }
        BAR1_128();   // all layer2 reads of s_outer1 done before state update rewrites it

        // ---- tile loop: mbarrier handshake with producers ----
        for (int kt = 0; kt < NKT; kt++) {
            MBAR_WAIT(smem_u32(&s_mbar[stage]), phase);   // full[stage]
            if (mac) {
                #pragma unroll
                for (int g = 0; g < BK; g += 4) {
                    float4 a0 = *(const float4*)&s_a[stage][rb + 0][g];
                    float4 a1 = *(const float4*)&s_a[stage][rb + 1][g];
                    float4 a2 = *(const float4*)&s_a[stage][rb + 2][g];
                    float4 a3 = *(const float4*)&s_a[stage][rb + 3][g];
                    ulonglong2 B0 = *(const ulonglong2*)&s_b[stage][g + 0][cg * 4];
                    ulonglong2 B1 = *(const ulonglong2*)&s_b[stage][g + 1][cg * 4];
                    ulonglong2 B2 = *(const ulonglong2*)&s_b[stage][g + 2][cg * 4];
                    ulonglong2 B3 = *(const ulonglong2*)&s_b[stage][g + 3][cg * 4];
                    #define MACROW(ai, i_) { \
                        unsigned long long dx, dy, dz, dw; \
                        DUP64(dx, ai.x); DUP64(dy, ai.y); DUP64(dz, ai.z); DUP64(dw, ai.w); \
                        FMA2(acc2[i_][0], dx, B0.x); FMA2(acc2[i_][0], dy, B1.x); \
                        FMA2(acc2[i_][0], dz, B2.x); FMA2(acc2[i_][0], dw, B3.x); \
                        FMA2(acc2[i_][1], dx, B0.y); FMA2(acc2[i_][1], dy, B1.y); \
                        FMA2(acc2[i_][1], dz, B2.y); FMA2(acc2[i_][1], dw, B3.y); }
                    MACROW(a0, 0) MACROW(a1, 1) MACROW(a2, 2) MACROW(a3, 3)
                    #undef MACROW
                }
            }
            MBAR_ARRIVE(smem_u32(&s_mbar[NSTAGE + stage]));  // empty[stage]
            if (++stage == NSTAGE) { stage = 0; phase ^= 1; }
        }

        // ---- layer1 state update (identical rounding chain, bitwise) ----
        if (mac) {
            #pragma unroll
            for (int i = 0; i < 4; i++) {
                const int lr = rb + i;
                #pragma unroll
                for (int p = 0; p < 2; p++) {
                    uint32_t ulo, uhi;
                    UNPK(ulo, uhi, acc2[i][p]);
                    #pragma unroll
                    for (int q = 0; q < 2; q++) {
                        const int   c    = cg * 4 + p * 2 + q;
                        const float accv = __uint_as_float(q ? uhi : ulo);
                        const float exc  = __fadd_rn(accv, s_b1[c]);
                        const float pre  = __fadd_rn(exc, __fmul_rn(inn[i][p * 2 + q], 0.9f));
                        const float outv = fmaxf(__fsub_rn(pre, 1.0f), 0.f);
                        const float gate = (pre > 1.0f) ? 1.0f : 0.0f;
                        inn[i][p * 2 + q] = __fsub_rn(pre, __fmul_rn(gate, __fmul_rn(1.5f, pre)));
                        s_outer1[lr][c] = outv;
                    }
                }
            }
        }
        BAR1_128();   // state-update writes visible to next step's layer2 reads
    }

    // ---- epilogue: log_softmax ----
    s_oacc[tid] = acca;
    if (tid < NCELL - NCONS) s_oacc[NCONS + tid] = accb;
    BAR1_128();
    if (tid < RPB) {
        float v[H2];
        float m = -INFINITY;
        #pragma unroll
        for (int n = 0; n < H2; n++) { v[n] = s_oacc[tid * H2 + n]; m = fmaxf(m, v[n]); }
        float s = 0.f;
        #pragma unroll
        for (int n = 0; n < H2; n++) s += expf(v[n] - m);
        const float ls = logf(s);
        #pragma unroll
        for (int n = 0; n < H2; n++) out[(r0 + tid) * H2 + n] = v[n] - m - ls;
    }
}

extern "C" void kernel_launch(void* const* d_in, const int* in_sizes, int n_in,
                              void* d_out, int out_size) {
    const float* x  = (const float*)d_in[0];
    const float* W1 = (const float*)d_in[1];
    const float* b1 = (const float*)d_in[2];
    const float* W2 = (const float*)d_in[3];
    const float* b2 = (const float*)d_in[4];
    spiking_all<<<NBLK, NTH>>>(x, W1, b1, W2, b2, (float*)d_out);
}